// round 11
// baseline (speedup 1.0000x reference)
#include <cuda_runtime.h>

// TopkWeightClusterLoss, algebraically reduced:
//   d2(q) = (x - q*s)^2 is convex in q => the 15-candidate sequence is V-shaped,
//   top-4 live at the outer q's. With y=|x| the top-4 multiset is exactly:
//     m0 = (y+7s)^2            (also the global max -> e0 = 1)
//     m1 = (y+6s)^2
//     m2 = (max(y+5s, 6s-y))^2
//     m3 = (max(y+4s, 7s-y))^2
//   loss_elem = S - D/E with e_i = exp(m_i - m0), E = 1+e1+e2+e3,
//   S = sum m_i, D = m0 + sum m_i*e_i.

#define ROWS 4096
#define COLS 4096
#define THREADS 256
#define L2E 1.4426950408889634f

__device__ float g_partial[ROWS];
__device__ unsigned int g_count = 0;

__device__ __forceinline__ float ex2f(float x) {
    float r; asm("ex2.approx.f32 %0, %1;" : "=f"(r) : "f"(x)); return r;
}
__device__ __forceinline__ float rcpf(float x) {
    float r; asm("rcp.approx.f32 %0, %1;" : "=f"(r) : "f"(x)); return r;
}

__device__ __forceinline__ float elem_loss(float x, float c4, float c5, float c6, float c7) {
    float y  = fabsf(x);
    float a0 = y + c7;
    float a1 = y + c6;
    float a2 = fmaxf(y + c5, c6 - y);
    float a3 = fmaxf(y + c4, c7 - y);
    float m0 = a0 * a0;
    float m1 = a1 * a1;
    float m2 = a2 * a2;
    float m3 = a3 * a3;
    float t  = -L2E * m0;                 // exp args: log2e*(m_i - m0)
    float e1 = ex2f(fmaf(m1, L2E, t));
    float e2 = ex2f(fmaf(m2, L2E, t));
    float e3 = ex2f(fmaf(m3, L2E, t));
    float E  = (1.0f + e1) + (e2 + e3);
    float S  = (m0 + m1) + (m2 + m3);
    float D  = fmaf(m3, e3, fmaf(m2, e2, fmaf(m1, e1, m0)));
    return fmaf(-D, rcpf(E), S);
}

__global__ __launch_bounds__(THREADS) void topk_loss_fused(
    const float* __restrict__ weight, const float* __restrict__ scale,
    float* __restrict__ out)
{
    const int row = blockIdx.x;
    const float s = __ldg(&scale[row]);
    const float c4 = 4.0f * s, c5 = 5.0f * s, c6 = 6.0f * s, c7 = 7.0f * s;

    const float4* wrow = reinterpret_cast<const float4*>(weight + (size_t)row * COLS);

    float acc = 0.0f;
#pragma unroll
    for (int it = 0; it < COLS / 4 / THREADS; ++it) {
        float4 v = wrow[it * THREADS + threadIdx.x];
        acc += elem_loss(v.x, c4, c5, c6, c7);
        acc += elem_loss(v.y, c4, c5, c6, c7);
        acc += elem_loss(v.z, c4, c5, c6, c7);
        acc += elem_loss(v.w, c4, c5, c6, c7);
    }

    // Deterministic block reduction.
    __shared__ float red[THREADS / 32];
    __shared__ bool s_last;
#pragma unroll
    for (int off = 16; off; off >>= 1)
        acc += __shfl_xor_sync(0xffffffffu, acc, off);
    if ((threadIdx.x & 31) == 0) red[threadIdx.x >> 5] = acc;
    __syncthreads();
    if (threadIdx.x == 0) {
        float v = 0.0f;
#pragma unroll
        for (int i = 0; i < THREADS / 32; ++i) v += red[i];
        g_partial[row] = v;
        __threadfence();
        unsigned int done = atomicAdd(&g_count, 1u);
        s_last = (done == (unsigned)(ROWS - 1));
    }
    __syncthreads();

    // Last block to finish performs the final (fixed-order => deterministic) reduce.
    if (s_last) {
        __threadfence();
        float a = 0.0f;
#pragma unroll
        for (int i = 0; i < ROWS / THREADS; ++i)
            a += g_partial[i * THREADS + threadIdx.x];
#pragma unroll
        for (int off = 16; off; off >>= 1)
            a += __shfl_xor_sync(0xffffffffu, a, off);
        if ((threadIdx.x & 31) == 0) red[threadIdx.x >> 5] = a;
        __syncthreads();
        if (threadIdx.x == 0) {
            float v = 0.0f;
#pragma unroll
            for (int i = 0; i < THREADS / 32; ++i) v += red[i];
            out[0] = v * (0.01f / 3.0f);   // COEFF / (TOPK-1)
            g_count = 0;                   // reset for next graph replay
        }
    }
}

extern "C" void kernel_launch(void* const* d_in, const int* in_sizes, int n_in,
                              void* d_out, int out_size)
{
    const float* weight = (const float*)d_in[0];
    const float* scale  = (const float*)d_in[1];
    float* out = (float*)d_out;

    topk_loss_fused<<<ROWS, THREADS>>>(weight, scale, out);
}

// round 12
// speedup vs baseline: 1.0011x; 1.0011x over previous
#include <cuda_runtime.h>

// TopkWeightClusterLoss, algebraically reduced:
//   d2(q) = (x - q*s)^2 is convex in q => the 15-candidate sequence is V-shaped,
//   top-4 live at the outer q's. With y=|x| the top-4 multiset is exactly:
//     m0 = (y+7s)^2            (also the global max -> e0 = 1)
//     m1 = (y+6s)^2
//     m2 = (max(y+5s, 6s-y))^2
//     m3 = (max(y+4s, 7s-y))^2
//   loss_elem = S - D/E with e_i = exp(m_i - m0), E = 1+e1+e2+e3,
//   S = sum m_i, D = m0 + sum m_i*e_i.

#define ROWS 4096
#define COLS 4096
#define THREADS 256
#define L2E 1.4426950408889634f

__device__ float g_partial[ROWS];
__device__ unsigned int g_count = 0;

__device__ __forceinline__ float ex2f(float x) {
    float r; asm("ex2.approx.f32 %0, %1;" : "=f"(r) : "f"(x)); return r;
}
__device__ __forceinline__ float rcpf(float x) {
    float r; asm("rcp.approx.f32 %0, %1;" : "=f"(r) : "f"(x)); return r;
}

__device__ __forceinline__ float elem_loss(float x, float c4, float c5, float c6, float c7) {
    float y  = fabsf(x);
    float a0 = y + c7;
    float a1 = y + c6;
    float a2 = fmaxf(y + c5, c6 - y);
    float a3 = fmaxf(y + c4, c7 - y);
    float m0 = a0 * a0;
    float m1 = a1 * a1;
    float m2 = a2 * a2;
    float m3 = a3 * a3;
    float t  = -L2E * m0;                 // exp args: log2e*(m_i - m0)
    float e1 = ex2f(fmaf(m1, L2E, t));
    float e2 = ex2f(fmaf(m2, L2E, t));
    float e3 = ex2f(fmaf(m3, L2E, t));
    float E  = (1.0f + e1) + (e2 + e3);
    float S  = (m0 + m1) + (m2 + m3);
    float D  = fmaf(m3, e3, fmaf(m2, e2, fmaf(m1, e1, m0)));
    return fmaf(-D, rcpf(E), S);
}

__global__ __launch_bounds__(THREADS) void topk_loss_fused(
    const float* __restrict__ weight, const float* __restrict__ scale,
    float* __restrict__ out)
{
    const int row = blockIdx.x;
    const float s = __ldg(&scale[row]);
    const float c4 = 4.0f * s, c5 = 5.0f * s, c6 = 6.0f * s, c7 = 7.0f * s;

    const float4* wrow = reinterpret_cast<const float4*>(weight + (size_t)row * COLS);

    float acc = 0.0f;
#pragma unroll
    for (int it = 0; it < COLS / 4 / THREADS; ++it) {
        float4 v = wrow[it * THREADS + threadIdx.x];
        acc += elem_loss(v.x, c4, c5, c6, c7);
        acc += elem_loss(v.y, c4, c5, c6, c7);
        acc += elem_loss(v.z, c4, c5, c6, c7);
        acc += elem_loss(v.w, c4, c5, c6, c7);
    }

    // Deterministic block reduction.
    __shared__ float red[THREADS / 32];
    __shared__ bool s_last;
#pragma unroll
    for (int off = 16; off; off >>= 1)
        acc += __shfl_xor_sync(0xffffffffu, acc, off);
    if ((threadIdx.x & 31) == 0) red[threadIdx.x >> 5] = acc;
    __syncthreads();
    if (threadIdx.x == 0) {
        float v = 0.0f;
#pragma unroll
        for (int i = 0; i < THREADS / 32; ++i) v += red[i];
        g_partial[row] = v;
        __threadfence();
        unsigned int done = atomicAdd(&g_count, 1u);
        s_last = (done == (unsigned)(ROWS - 1));
    }
    __syncthreads();

    // Last block to finish performs the final (fixed-order => deterministic) reduce.
    if (s_last) {
        __threadfence();
        float a = 0.0f;
#pragma unroll
        for (int i = 0; i < ROWS / THREADS; ++i)
            a += g_partial[i * THREADS + threadIdx.x];
#pragma unroll
        for (int off = 16; off; off >>= 1)
            a += __shfl_xor_sync(0xffffffffu, a, off);
        if ((threadIdx.x & 31) == 0) red[threadIdx.x >> 5] = a;
        __syncthreads();
        if (threadIdx.x == 0) {
            float v = 0.0f;
#pragma unroll
            for (int i = 0; i < THREADS / 32; ++i) v += red[i];
            out[0] = v * (0.01f / 3.0f);   // COEFF / (TOPK-1)
            g_count = 0;                   // reset for next graph replay
        }
    }
}

extern "C" void kernel_launch(void* const* d_in, const int* in_sizes, int n_in,
                              void* d_out, int out_size)
{
    const float* weight = (const float*)d_in[0];
    const float* scale  = (const float*)d_in[1];
    float* out = (float*)d_out;

    topk_loss_fused<<<ROWS, THREADS>>>(weight, scale, out);
}

// round 14
// speedup vs baseline: 1.0729x; 1.0718x over previous
#include <cuda_runtime.h>

// TopkWeightClusterLoss, algebraically reduced + f32x2-packed (sm_103a).
// Top-4 multiset (y=|x|):
//   m0=(y+7s)^2 (global max), m1=(y+6s)^2,
//   m2=(5.5s+|y-0.5s|)^2, m3=(5.5s+|y-1.5s|)^2   [max/abs identity]
// elem loss = S - D/E, e_i=exp(m_i-m0), E=1+e1+e2+e3, S=sum m_i, D=m0+sum m_i e_i.
// Divisions batched 4-wide: one rcp per 4 elements.

#define ROWS 4096
#define COLS 4096
#define THREADS 256

typedef unsigned long long ull;

#define L2EP  0x3FB8AA3B3FB8AA3BULL   // packed  log2(e)
#define NL2EP 0xBFB8AA3BBFB8AA3BULL   // packed -log2(e)
#define ONEP  0x3F8000003F800000ULL   // packed 1.0f

__device__ float g_partial[ROWS];
__device__ unsigned int g_count = 0;

__device__ __forceinline__ ull pk(float lo, float hi) {
    ull r; asm("mov.b64 %0, {%1,%2};" : "=l"(r) : "f"(lo), "f"(hi)); return r;
}
__device__ __forceinline__ void upk(float& lo, float& hi, ull p) {
    asm("mov.b64 {%0,%1}, %2;" : "=f"(lo), "=f"(hi) : "l"(p));
}
__device__ __forceinline__ ull addx2(ull a, ull b) {
    ull r; asm("add.rn.f32x2 %0, %1, %2;" : "=l"(r) : "l"(a), "l"(b)); return r;
}
__device__ __forceinline__ ull mulx2(ull a, ull b) {
    ull r; asm("mul.rn.f32x2 %0, %1, %2;" : "=l"(r) : "l"(a), "l"(b)); return r;
}
__device__ __forceinline__ ull fmax2(ull a, ull b, ull c) {
    ull r; asm("fma.rn.f32x2 %0, %1, %2, %3;" : "=l"(r) : "l"(a), "l"(b), "l"(c)); return r;
}
__device__ __forceinline__ ull abs2(ull a) {
    ull r; asm("and.b64 %0, %1, 0x7FFFFFFF7FFFFFFF;" : "=l"(r) : "l"(a)); return r;
}
__device__ __forceinline__ float ex2f(float x) {
    float r; asm("ex2.approx.f32 %0, %1;" : "=f"(r) : "f"(x)); return r;
}
__device__ __forceinline__ float rcpf(float x) {
    float r; asm("rcp.approx.f32 %0, %1;" : "=f"(r) : "f"(x)); return r;
}

// Process one packed pair of elements; emit per-element E, D; accumulate S packed.
__device__ __forceinline__ void pair_ED(
    ull xp, ull c7p, ull c6p, ull nc05p, ull nc15p, ull c55p,
    ull& accSp, float& E0, float& E1, float& D0, float& D1)
{
    ull yp  = abs2(xp);
    ull a0p = addx2(yp, c7p);
    ull a1p = addx2(yp, c6p);
    ull a2p = addx2(abs2(addx2(yp, nc05p)), c55p);
    ull a3p = addx2(abs2(addx2(yp, nc15p)), c55p);

    ull m0p = mulx2(a0p, a0p);
    ull m1p = mulx2(a1p, a1p);
    ull m2p = mulx2(a2p, a2p);
    ull m3p = mulx2(a3p, a3p);

    ull tp  = mulx2(m0p, (ull)NL2EP);
    ull g1p = fmax2(m1p, (ull)L2EP, tp);
    ull g2p = fmax2(m2p, (ull)L2EP, tp);
    ull g3p = fmax2(m3p, (ull)L2EP, tp);

    float g1l, g1h, g2l, g2h, g3l, g3h;
    upk(g1l, g1h, g1p); upk(g2l, g2h, g2p); upk(g3l, g3h, g3p);
    ull e1p = pk(ex2f(g1l), ex2f(g1h));
    ull e2p = pk(ex2f(g2l), ex2f(g2h));
    ull e3p = pk(ex2f(g3l), ex2f(g3h));

    ull Ep = addx2(addx2(e1p, e2p), addx2(e3p, (ull)ONEP));
    ull Dp = fmax2(m3p, e3p, fmax2(m2p, e2p, fmax2(m1p, e1p, m0p)));
    accSp  = addx2(accSp, addx2(addx2(m0p, m1p), addx2(m2p, m3p)));

    upk(E0, E1, Ep);
    upk(D0, D1, Dp);
}

__global__ __launch_bounds__(THREADS) void topk_loss_fused(
    const float* __restrict__ weight, const float* __restrict__ scale,
    float* __restrict__ out)
{
    const int row = blockIdx.x;
    const float s = __ldg(&scale[row]);
    const ull c7p   = pk(7.0f * s, 7.0f * s);
    const ull c6p   = pk(6.0f * s, 6.0f * s);
    const ull nc05p = pk(-0.5f * s, -0.5f * s);
    const ull nc15p = pk(-1.5f * s, -1.5f * s);
    const ull c55p  = pk(5.5f * s, 5.5f * s);

    const float4* wrow = reinterpret_cast<const float4*>(weight + (size_t)row * COLS);

    ull accSp = 0ULL;      // packed (0.0f, 0.0f)
    float accD = 0.0f;

#pragma unroll
    for (int it = 0; it < COLS / 4 / THREADS; ++it) {
        float4 v = wrow[it * THREADS + threadIdx.x];
        float E0, E1, E2, E3, D0, D1, D2, D3;
        pair_ED(pk(v.x, v.y), c7p, c6p, nc05p, nc15p, c55p, accSp, E0, E1, D0, D1);
        pair_ED(pk(v.z, v.w), c7p, c6p, nc05p, nc15p, c55p, accSp, E2, E3, D2, D3);

        // Batched divide: D0/E0 + D1/E1 + D2/E2 + D3/E3 with one rcp.
        float n01 = fmaf(D1, E0, D0 * E1);
        float e01 = E0 * E1;
        float n23 = fmaf(D3, E2, D2 * E3);
        float e23 = E2 * E3;
        float N   = fmaf(n23, e01, n01 * e23);
        float Et  = e01 * e23;
        accD = fmaf(N, rcpf(Et), accD);
    }

    float sl, sh;
    upk(sl, sh, accSp);
    float acc = (sl + sh) - accD;

    // Deterministic block reduction.
    __shared__ float red[THREADS / 32];
    __shared__ bool s_last;
#pragma unroll
    for (int off = 16; off; off >>= 1)
        acc += __shfl_xor_sync(0xffffffffu, acc, off);
    if ((threadIdx.x & 31) == 0) red[threadIdx.x >> 5] = acc;
    __syncthreads();
    if (threadIdx.x == 0) {
        float v = 0.0f;
#pragma unroll
        for (int i = 0; i < THREADS / 32; ++i) v += red[i];
        g_partial[row] = v;
        __threadfence();
        unsigned int done = atomicAdd(&g_count, 1u);
        s_last = (done == (unsigned)(ROWS - 1));
    }
    __syncthreads();

    // Last block performs the final fixed-order (deterministic) reduce.
    if (s_last) {
        __threadfence();
        float a = 0.0f;
#pragma unroll
        for (int i = 0; i < ROWS / THREADS; ++i)
            a += g_partial[i * THREADS + threadIdx.x];
#pragma unroll
        for (int off = 16; off; off >>= 1)
            a += __shfl_xor_sync(0xffffffffu, a, off);
        if ((threadIdx.x & 31) == 0) red[threadIdx.x >> 5] = a;
        __syncthreads();
        if (threadIdx.x == 0) {
            float v = 0.0f;
#pragma unroll
            for (int i = 0; i < THREADS / 32; ++i) v += red[i];
            out[0] = v * (0.01f / 3.0f);   // COEFF / (TOPK-1)
            g_count = 0;                   // reset for next graph replay
        }
    }
}

extern "C" void kernel_launch(void* const* d_in, const int* in_sizes, int n_in,
                              void* d_out, int out_size)
{
    const float* weight = (const float*)d_in[0];
    const float* scale  = (const float*)d_in[1];
    float* out = (float*)d_out;

    topk_loss_fused<<<ROWS, THREADS>>>(weight, scale, out);
}

// round 17
// speedup vs baseline: 1.0755x; 1.0024x over previous
#include <cuda_runtime.h>

// TopkWeightClusterLoss, algebraically reduced + f32x2-packed (sm_103a).
// Top-4 multiset (y=|x|):
//   m0=(y+7s)^2 (global max), m1=(y+6s)^2,
//   m2=(5.5s+|y-0.5s|)^2, m3=(5.5s+|y-1.5s|)^2   [max/abs identity]
// elem loss = S - D/E, e_i=exp(m_i-m0), E=1+e1+e2+e3, S=sum m_i, D=m0+sum m_i e_i.
// Divisions batched 4-wide: one rcp per 4 elements.

#define ROWS 4096
#define COLS 4096
#define THREADS 256

typedef unsigned long long ull;

#define L2EP  0x3FB8AA3B3FB8AA3BULL   // packed  log2(e)
#define NL2EP 0xBFB8AA3BBFB8AA3BULL   // packed -log2(e)
#define ONEP  0x3F8000003F800000ULL   // packed 1.0f

__device__ float g_partial[ROWS];
__device__ unsigned int g_count = 0;

__device__ __forceinline__ ull pk(float lo, float hi) {
    ull r; asm("mov.b64 %0, {%1,%2};" : "=l"(r) : "f"(lo), "f"(hi)); return r;
}
__device__ __forceinline__ void upk(float& lo, float& hi, ull p) {
    asm("mov.b64 {%0,%1}, %2;" : "=f"(lo), "=f"(hi) : "l"(p));
}
__device__ __forceinline__ ull addx2(ull a, ull b) {
    ull r; asm("add.rn.f32x2 %0, %1, %2;" : "=l"(r) : "l"(a), "l"(b)); return r;
}
__device__ __forceinline__ ull mulx2(ull a, ull b) {
    ull r; asm("mul.rn.f32x2 %0, %1, %2;" : "=l"(r) : "l"(a), "l"(b)); return r;
}
__device__ __forceinline__ ull fmax2(ull a, ull b, ull c) {
    ull r; asm("fma.rn.f32x2 %0, %1, %2, %3;" : "=l"(r) : "l"(a), "l"(b), "l"(c)); return r;
}
__device__ __forceinline__ ull abs2(ull a) {
    ull r; asm("and.b64 %0, %1, 0x7FFFFFFF7FFFFFFF;" : "=l"(r) : "l"(a)); return r;
}
__device__ __forceinline__ float ex2f(float x) {
    float r; asm("ex2.approx.f32 %0, %1;" : "=f"(r) : "f"(x)); return r;
}
__device__ __forceinline__ float rcpf(float x) {
    float r; asm("rcp.approx.f32 %0, %1;" : "=f"(r) : "f"(x)); return r;
}

// Process one packed pair of elements; emit per-element E, D; accumulate S packed.
__device__ __forceinline__ void pair_ED(
    ull xp, ull c7p, ull c6p, ull nc05p, ull nc15p, ull c55p,
    ull& accSp, float& E0, float& E1, float& D0, float& D1)
{
    ull yp  = abs2(xp);
    ull a0p = addx2(yp, c7p);
    ull a1p = addx2(yp, c6p);
    ull a2p = addx2(abs2(addx2(yp, nc05p)), c55p);
    ull a3p = addx2(abs2(addx2(yp, nc15p)), c55p);

    ull m0p = mulx2(a0p, a0p);
    ull m1p = mulx2(a1p, a1p);
    ull m2p = mulx2(a2p, a2p);
    ull m3p = mulx2(a3p, a3p);

    ull tp  = mulx2(m0p, (ull)NL2EP);
    ull g1p = fmax2(m1p, (ull)L2EP, tp);
    ull g2p = fmax2(m2p, (ull)L2EP, tp);
    ull g3p = fmax2(m3p, (ull)L2EP, tp);

    float g1l, g1h, g2l, g2h, g3l, g3h;
    upk(g1l, g1h, g1p); upk(g2l, g2h, g2p); upk(g3l, g3h, g3p);
    ull e1p = pk(ex2f(g1l), ex2f(g1h));
    ull e2p = pk(ex2f(g2l), ex2f(g2h));
    ull e3p = pk(ex2f(g3l), ex2f(g3h));

    ull Ep = addx2(addx2(e1p, e2p), addx2(e3p, (ull)ONEP));
    ull Dp = fmax2(m3p, e3p, fmax2(m2p, e2p, fmax2(m1p, e1p, m0p)));
    accSp  = addx2(accSp, addx2(addx2(m0p, m1p), addx2(m2p, m3p)));

    upk(E0, E1, Ep);
    upk(D0, D1, Dp);
}

__global__ __launch_bounds__(THREADS) void topk_loss_fused(
    const float* __restrict__ weight, const float* __restrict__ scale,
    float* __restrict__ out)
{
    const int row = blockIdx.x;
    const float s = __ldg(&scale[row]);
    const ull c7p   = pk(7.0f * s, 7.0f * s);
    const ull c6p   = pk(6.0f * s, 6.0f * s);
    const ull nc05p = pk(-0.5f * s, -0.5f * s);
    const ull nc15p = pk(-1.5f * s, -1.5f * s);
    const ull c55p  = pk(5.5f * s, 5.5f * s);

    const float4* wrow = reinterpret_cast<const float4*>(weight + (size_t)row * COLS);

    ull accSp = 0ULL;      // packed (0.0f, 0.0f)
    float accD = 0.0f;

#pragma unroll
    for (int it = 0; it < COLS / 4 / THREADS; ++it) {
        float4 v = wrow[it * THREADS + threadIdx.x];
        float E0, E1, E2, E3, D0, D1, D2, D3;
        pair_ED(pk(v.x, v.y), c7p, c6p, nc05p, nc15p, c55p, accSp, E0, E1, D0, D1);
        pair_ED(pk(v.z, v.w), c7p, c6p, nc05p, nc15p, c55p, accSp, E2, E3, D2, D3);

        // Batched divide: D0/E0 + D1/E1 + D2/E2 + D3/E3 with one rcp.
        float n01 = fmaf(D1, E0, D0 * E1);
        float e01 = E0 * E1;
        float n23 = fmaf(D3, E2, D2 * E3);
        float e23 = E2 * E3;
        float N   = fmaf(n23, e01, n01 * e23);
        float Et  = e01 * e23;
        accD = fmaf(N, rcpf(Et), accD);
    }

    float sl, sh;
    upk(sl, sh, accSp);
    float acc = (sl + sh) - accD;

    // Deterministic block reduction.
    __shared__ float red[THREADS / 32];
    __shared__ bool s_last;
#pragma unroll
    for (int off = 16; off; off >>= 1)
        acc += __shfl_xor_sync(0xffffffffu, acc, off);
    if ((threadIdx.x & 31) == 0) red[threadIdx.x >> 5] = acc;
    __syncthreads();
    if (threadIdx.x == 0) {
        float v = 0.0f;
#pragma unroll
        for (int i = 0; i < THREADS / 32; ++i) v += red[i];
        g_partial[row] = v;
        __threadfence();
        unsigned int done = atomicAdd(&g_count, 1u);
        s_last = (done == (unsigned)(ROWS - 1));
    }
    __syncthreads();

    // Last block performs the final fixed-order (deterministic) reduce.
    if (s_last) {
        __threadfence();
        float a = 0.0f;
#pragma unroll
        for (int i = 0; i < ROWS / THREADS; ++i)
            a += g_partial[i * THREADS + threadIdx.x];
#pragma unroll
        for (int off = 16; off; off >>= 1)
            a += __shfl_xor_sync(0xffffffffu, a, off);
        if ((threadIdx.x & 31) == 0) red[threadIdx.x >> 5] = a;
        __syncthreads();
        if (threadIdx.x == 0) {
            float v = 0.0f;
#pragma unroll
            for (int i = 0; i < THREADS / 32; ++i) v += red[i];
            out[0] = v * (0.01f / 3.0f);   // COEFF / (TOPK-1)
            g_count = 0;                   // reset for next graph replay
        }
    }
}

extern "C" void kernel_launch(void* const* d_in, const int* in_sizes, int n_in,
                              void* d_out, int out_size)
{
    const float* weight = (const float*)d_in[0];
    const float* scale  = (const float*)d_in[1];
    float* out = (float*)d_out;

    topk_loss_fused<<<ROWS, THREADS>>>(weight, scale, out);
}